// round 1
// baseline (speedup 1.0000x reference)
#include <cuda_runtime.h>
#include <cuda_bf16.h>

// Problem constants (from reference)
#define GX 352
#define GY 400
#define GZ 1
#define BSZ 4
#define NSEG (BSZ * GZ * GY * GX)   // 563200
#define NPTS 2000000
#define CH 4

// Output layout: [ mean: NSEG*4 f32 ][ counts: NSEG f32 ]  (concatenated tuple)

__global__ void zero_out_kernel(float4* __restrict__ out4, int n4) {
    int i = blockIdx.x * blockDim.x + threadIdx.x;
    int stride = gridDim.x * blockDim.x;
    for (; i < n4; i += stride) {
        out4[i] = make_float4(0.f, 0.f, 0.f, 0.f);
    }
}

__global__ void scatter_kernel(const float4* __restrict__ feats,
                               const int4* __restrict__ coors,
                               float4* __restrict__ sums,
                               float* __restrict__ counts,
                               int n) {
    int i = blockIdx.x * blockDim.x + threadIdx.x;
    int stride = gridDim.x * blockDim.x;
    for (; i < n; i += stride) {
        int4 c = coors[i];            // b, z, y, x
        int seg = ((c.x * GZ + c.y) * GY + c.z) * GX + c.w;
        float4 f = feats[i];
        atomicAdd(&sums[seg], f);     // sm_90+: single vec4 RED to L2
        atomicAdd(&counts[seg], 1.0f);
    }
}

__global__ void finalize_kernel(float4* __restrict__ sums,
                                const float* __restrict__ counts,
                                int nseg) {
    int s = blockIdx.x * blockDim.x + threadIdx.x;
    int stride = gridDim.x * blockDim.x;
    for (; s < nseg; s += stride) {
        float cnt = counts[s];
        float inv = 1.0f / fmaxf(cnt, 1.0f);
        float4 v = sums[s];
        v.x *= inv; v.y *= inv; v.z *= inv; v.w *= inv;
        sums[s] = v;                  // in-place: sums -> mean
    }
}

extern "C" void kernel_launch(void* const* d_in, const int* in_sizes, int n_in,
                              void* d_out, int out_size) {
    const float4* feats = (const float4*)d_in[0];   // (NPTS, 4) f32
    const int4*   coors = (const int4*)d_in[1];     // (NPTS, 4) i32
    float* out = (float*)d_out;

    float4* sums  = (float4*)out;            // NSEG float4
    float*  counts = out + (size_t)NSEG * CH; // NSEG floats

    // 1) zero the whole output (mean sums + counts): 704000 float4s
    {
        int n4 = (NSEG * CH + NSEG) / 4;     // 704000
        int threads = 256;
        int blocks = (n4 + threads - 1) / threads;
        if (blocks > 8192) blocks = 8192;
        zero_out_kernel<<<blocks, threads>>>((float4*)out, n4);
    }

    // 2) scatter-add features and counts
    {
        int threads = 256;
        int blocks = (NPTS + threads - 1) / threads;
        scatter_kernel<<<blocks, threads>>>(feats, coors, sums, counts, NPTS);
    }

    // 3) divide sums by max(count,1) in place
    {
        int threads = 256;
        int blocks = (NSEG + threads - 1) / threads;
        finalize_kernel<<<blocks, threads>>>(sums, counts, NSEG);
    }
}